// round 14
// baseline (speedup 1.0000x reference)
#include <cuda_runtime.h>
#include <cuda_bf16.h>
#include <cstdint>
#include <cstddef>

#define Bn 8
#define Tn 2048
#define Dn 128
#define NPART (Bn * 16 * 16)   // 2048 CTAs / partials

// ---- scratch (static device globals; no allocations) ----
__device__ __nv_bfloat16 g_zbf[Bn * Tn * Dn];   // 4 MB
__device__ float        g_z2[Bn * Tn];          // 64 KB
__device__ double       g_part[NPART];          // per-CTA partials
__device__ int          g_ticket;               // zero-init; last CTA resets

__device__ __forceinline__ uint32_t smem_u32(const void* p) {
    uint32_t a;
    asm("{ .reg .u64 t; cvta.to.shared.u64 t, %1; cvt.u32.u64 %0, t; }"
        : "=r"(a) : "l"(p));
    return a;
}

#define LDSM_X4(r0, r1, r2, r3, a) \
    asm volatile("ldmatrix.sync.aligned.m8n8.x4.shared.b16 {%0,%1,%2,%3}, [%4];" \
                 : "=r"(r0), "=r"(r1), "=r"(r2), "=r"(r3) : "r"(a))

// ============================================================
// Kernel 1: bf16 cast of z + per-row squared norms (4 rows/warp)
// ============================================================
__global__ void __launch_bounds__(256) prep_kernel(const float* __restrict__ z) {
    const int warp = threadIdx.x >> 5, lane = threadIdx.x & 31;
    const int row0 = blockIdx.x * 32 + warp * 4;
    float4 v[4];
    #pragma unroll
    for (int r = 0; r < 4; r++)
        v[r] = ((const float4*)(z + (size_t)(row0 + r) * Dn))[lane];

    #pragma unroll
    for (int r = 0; r < 4; r++) {
        __nv_bfloat162 p0 = __floats2bfloat162_rn(v[r].x, v[r].y);
        __nv_bfloat162 p1 = __floats2bfloat162_rn(v[r].z, v[r].w);
        uint2 o;
        o.x = *reinterpret_cast<uint32_t*>(&p0);
        o.y = *reinterpret_cast<uint32_t*>(&p1);
        ((uint2*)g_zbf)[(size_t)(row0 + r) * 32 + lane] = o;
    }

    float s[4];
    #pragma unroll
    for (int r = 0; r < 4; r++)
        s[r] = v[r].x * v[r].x + v[r].y * v[r].y + v[r].z * v[r].z + v[r].w * v[r].w;
    #pragma unroll
    for (int off = 16; off; off >>= 1) {
        #pragma unroll
        for (int r = 0; r < 4; r++)
            s[r] += __shfl_xor_sync(0xffffffffu, s[r], off);
    }
    if (lane == 0) {
        #pragma unroll
        for (int r = 0; r < 4; r++) g_z2[row0 + r] = s[r];
    }
}

// ============================================================
// Kernel 2: fused Gram(MMA) -> smem Gram bounce -> warp-per-row
// coalesced epilogue -> fused last-CTA reduce
// grid = (16, 16, 8) = (jt, it, b); 256 threads (8 warps, 4x2)
// ============================================================
#define SM_WSTRIDE 68
#define GST 130     // Gram smem stride (floats); 128x130x4 = 66560 B
#define SMEM_BYTES (2 * 128 * SM_WSTRIDE * 4 + 2 * 128 * 4)

extern __shared__ unsigned char smem_raw[];

__global__ void __launch_bounds__(256, 2)
main_kernel(const float* __restrict__ gt, const float* __restrict__ sigma,
            float* __restrict__ out) {
    uint32_t* zi  = (uint32_t*)smem_raw;
    uint32_t* zj  = zi + 128 * SM_WSTRIDE;
    float*    Gsm = (float*)smem_raw;            // reused after MMA
    float*    z2i = (float*)(zj + 128 * SM_WSTRIDE);
    float*    z2j = z2i + 128;

    const int jt = blockIdx.x, it = blockIdx.y, b = blockIdx.z;
    const int i0 = it * 128, j0 = jt * 128;
    const int tid = threadIdx.x;
    const int warp = tid >> 5, lane = tid & 31;

    // ---- L2 prefetch of this CTA's 128KB gt tile (overlaps MMA phase) ----
    {
        const char* gbase = (const char*)gt;
        #pragma unroll
        for (int p = 0; p < 4; p++) {
            int idx = tid + p * 256;                 // 0..1023
            int r = idx >> 3, c = idx & 7;
            const char* addr = gbase +
                ((size_t)(b * Tn + i0 + r) * Tn + j0) * 8 + (size_t)c * 128;
            asm volatile("prefetch.global.L2 [%0];" :: "l"(addr));
        }
    }

    // ---- load z tiles (bf16, 16B vectors) ----
    const uint4* zsrc = (const uint4*)g_zbf;     // one row = 16 uint4
    #pragma unroll
    for (int p = 0; p < 8; p++) {
        int idx = tid + p * 256;                 // 0..2047
        int r = idx >> 4, c = idx & 15;
        uint4 vi = zsrc[(size_t)(b * Tn + i0 + r) * 16 + c];
        *((uint4*)(zi + r * SM_WSTRIDE + c * 4)) = vi;
        uint4 vj = zsrc[(size_t)(b * Tn + j0 + r) * 16 + c];
        *((uint4*)(zj + r * SM_WSTRIDE + c * 4)) = vj;
    }
    if (tid < 128) z2i[tid] = g_z2[b * Tn + i0 + tid];
    else           z2j[tid - 128] = g_z2[b * Tn + j0 + (tid - 128)];
    __syncthreads();

    // ---- Gram 128x128 via mma.sync m16n8k16 bf16, ldmatrix operands ----
    const int wm = warp & 3, wn = warp >> 2;     // 4 x 2 warp grid
    const int rowBase = wm * 32, colBase = wn * 64;
    const int gr = lane >> 2, q = lane & 3;

    const uint32_t ziB = smem_u32(zi), zjB = smem_u32(zj);
    const int la = lane & 15, ha = lane >> 4;
    uint32_t aAddr0 = ziB + (uint32_t)((rowBase + la) * SM_WSTRIDE + ha * 4) * 4;
    uint32_t aAddr1 = aAddr0 + 16 * SM_WSTRIDE * 4;
    const int gq = lane >> 3;
    uint32_t bAddr = zjB + (uint32_t)((colBase + (gq >> 1) * 8 + (lane & 7)) * SM_WSTRIDE
                                      + (gq & 1) * 4) * 4;
    const uint32_t FN_STRIDE = 16 * SM_WSTRIDE * 4;

    float acc[2][8][4];
    #pragma unroll
    for (int fm = 0; fm < 2; fm++)
        #pragma unroll
        for (int fn = 0; fn < 8; fn++)
            #pragma unroll
            for (int v = 0; v < 4; v++) acc[fm][fn][v] = 0.f;

    #pragma unroll
    for (int ks = 0; ks < 8; ks++) {
        const uint32_t ko = ks * 32;
        uint32_t a[2][4], bb[4][4];
        LDSM_X4(a[0][0], a[0][1], a[0][2], a[0][3], aAddr0 + ko);
        LDSM_X4(a[1][0], a[1][1], a[1][2], a[1][3], aAddr1 + ko);
        #pragma unroll
        for (int p = 0; p < 4; p++)
            LDSM_X4(bb[p][0], bb[p][1], bb[p][2], bb[p][3], bAddr + p * FN_STRIDE + ko);

        #pragma unroll
        for (int p = 0; p < 4; p++) {
            #pragma unroll
            for (int s = 0; s < 2; s++) {
                const int fn = 2 * p + s;
                const uint32_t b0 = bb[p][2 * s], b1 = bb[p][2 * s + 1];
                #pragma unroll
                for (int fm = 0; fm < 2; fm++) {
                    asm volatile(
                        "mma.sync.aligned.m16n8k16.row.col.f32.bf16.bf16.f32 "
                        "{%0,%1,%2,%3}, {%4,%5,%6,%7}, {%8,%9}, {%0,%1,%2,%3};"
                        : "+f"(acc[fm][fn][0]), "+f"(acc[fm][fn][1]),
                          "+f"(acc[fm][fn][2]), "+f"(acc[fm][fn][3])
                        : "r"(a[fm][0]), "r"(a[fm][1]), "r"(a[fm][2]), "r"(a[fm][3]),
                          "r"(b0), "r"(b1));
                }
            }
        }
    }
    __syncthreads();   // all LDSM done; zi/zj may be overwritten

    // ---- bounce Gram fragments to smem (frees acc for the epilogue) ----
    #pragma unroll
    for (int fm = 0; fm < 2; fm++) {
        const int r0 = rowBase + fm * 16 + gr;
        #pragma unroll
        for (int fn = 0; fn < 8; fn++) {
            const int c = colBase + fn * 8 + 2 * q;
            *((float2*)(Gsm + (size_t)r0 * GST + c)) =
                make_float2(acc[fm][fn][0], acc[fm][fn][1]);
            *((float2*)(Gsm + (size_t)(r0 + 8) * GST + c)) =
                make_float2(acc[fm][fn][2], acc[fm][fn][3]);
        }
    }
    __syncthreads();

    // ---- epilogue: warp-per-row, fully coalesced gt stream ----
    const float sg0 = sigma[0], sg1 = sigma[1];
    const float c0 = 1.0f / (2.0f * sg0 * sg0), c1 = 1.0f / (2.0f * sg1 * sg1);
    const float4* gt4 = (const float4*)gt;
    float sum = 0.f;

    // z2j pairs for this lane (invariant over rows)
    const float2 zjlo = *((const float2*)(z2j + 2 * lane));        // j = 2l, 2l+1
    const float2 zjhi = *((const float2*)(z2j + 64 + 2 * lane));   // j = 64+2l, +1

    const int row0 = warp * 16;
    size_t fidx = (((size_t)(b * Tn + i0 + row0) * Tn) + j0) >> 1; // float4 units
    #pragma unroll 4
    for (int r = 0; r < 16; r++) {
        const int row = row0 + r;
        const float z2r = z2i[row];
        const float4 gA = __ldcg(gt4 + fidx + lane);        // j = 2l, 2l+1
        const float4 gB = __ldcg(gt4 + fidx + 32 + lane);   // j = 64+2l, +1
        const float2 GA = *((const float2*)(Gsm + (size_t)row * GST + 2 * lane));
        const float2 GB = *((const float2*)(Gsm + (size_t)row * GST + 64 + 2 * lane));
        const float w00 = __expf(-(gA.x * gA.x * c0 + gA.y * gA.y * c1));
        const float w01 = __expf(-(gA.z * gA.z * c0 + gA.w * gA.w * c1));
        const float w10 = __expf(-(gB.x * gB.x * c0 + gB.y * gB.y * c1));
        const float w11 = __expf(-(gB.z * gB.z * c0 + gB.w * gB.w * c1));
        sum += w00 * (z2r + zjlo.x - 2.f * GA.x);
        sum += w01 * (z2r + zjlo.y - 2.f * GA.y);
        sum += w10 * (z2r + zjhi.x - 2.f * GB.x);
        sum += w11 * (z2r + zjhi.y - 2.f * GB.y);
        fidx += (size_t)(Tn / 2);
    }

    // ---- block reduce -> per-CTA partial ----
    #pragma unroll
    for (int o = 16; o; o >>= 1) sum += __shfl_xor_sync(0xffffffffu, sum, o);
    __shared__ float wsum[8];
    __shared__ int isLast;
    if (lane == 0) wsum[warp] = sum;
    __syncthreads();
    if (tid == 0) {
        float t = 0.f;
        #pragma unroll
        for (int w = 0; w < 8; w++) t += wsum[w];
        g_part[(b * 16 + it) * 16 + jt] = (double)t;
        __threadfence();
        int old = atomicAdd(&g_ticket, 1);
        isLast = (old == NPART - 1);
    }
    __syncthreads();

    // ---- last CTA: deterministic final reduce (fixed index order) ----
    if (isLast) {
        double s = 0.0;
        #pragma unroll
        for (int k = 0; k < NPART / 256; k++)
            s += g_part[tid * (NPART / 256) + k];
        __shared__ double sh[256];
        sh[tid] = s;
        __syncthreads();
        for (int o = 128; o; o >>= 1) {
            if (tid < o) sh[tid] += sh[tid + o];
            __syncthreads();
        }
        if (tid == 0) {
            out[0] = (float)(sh[0] / ((double)Bn * (double)Tn * (double)Tn));
            g_ticket = 0;   // reset for next graph replay
        }
    }
}

// ============================================================
extern "C" void kernel_launch(void* const* d_in, const int* in_sizes, int n_in,
                              void* d_out, int out_size) {
    const float *z = nullptr, *gt = nullptr, *sg = nullptr;
    for (int i = 0; i < n_in; i++) {
        if (in_sizes[i] == Bn * Tn * Dn)      z  = (const float*)d_in[i];
        else if (in_sizes[i] == 2)            sg = (const float*)d_in[i];
        else                                  gt = (const float*)d_in[i];
    }

    cudaFuncSetAttribute(main_kernel,
                         cudaFuncAttributeMaxDynamicSharedMemorySize, SMEM_BYTES);

    prep_kernel<<<Bn * Tn / 32, 256>>>(z);
    dim3 grid(16, 16, Bn);
    main_kernel<<<grid, 256, SMEM_BYTES>>>(gt, sg, (float*)d_out);
}

// round 15
// speedup vs baseline: 1.1114x; 1.1114x over previous
#include <cuda_runtime.h>
#include <cuda_bf16.h>
#include <cstdint>
#include <cstddef>

#define Bn 8
#define Tn 2048
#define Dn 128
#define NPART (Bn * 16 * 16)   // 2048 CTAs / partials

// ---- scratch (static device globals; no allocations) ----
__device__ float  g_z2[Bn * Tn];          // 64 KB row norms
__device__ double g_part[NPART];          // per-CTA partials
__device__ int    g_ticket;               // zero-init; last CTA resets

__device__ __forceinline__ uint32_t smem_u32(const void* p) {
    uint32_t a;
    asm("{ .reg .u64 t; cvta.to.shared.u64 t, %1; cvt.u32.u64 %0, t; }"
        : "=r"(a) : "l"(p));
    return a;
}

#define LDSM_X4(r0, r1, r2, r3, a) \
    asm volatile("ldmatrix.sync.aligned.m8n8.x4.shared.b16 {%0,%1,%2,%3}, [%4];" \
                 : "=r"(r0), "=r"(r1), "=r"(r2), "=r"(r3) : "r"(a))

// ============================================================
// Kernel 1: per-row squared norms only (no bf16 materialization)
// 4 rows/warp; reads 8MB, writes 64KB.
// ============================================================
__global__ void __launch_bounds__(256) z2_kernel(const float* __restrict__ z) {
    const int warp = threadIdx.x >> 5, lane = threadIdx.x & 31;
    const int row0 = blockIdx.x * 32 + warp * 4;
    float s[4];
    #pragma unroll
    for (int r = 0; r < 4; r++) {
        const float4 v = ((const float4*)(z + (size_t)(row0 + r) * Dn))[lane];
        s[r] = v.x * v.x + v.y * v.y + v.z * v.z + v.w * v.w;
    }
    #pragma unroll
    for (int off = 16; off; off >>= 1) {
        #pragma unroll
        for (int r = 0; r < 4; r++)
            s[r] += __shfl_xor_sync(0xffffffffu, s[r], off);
    }
    if (lane == 0) {
        #pragma unroll
        for (int r = 0; r < 4; r++) g_z2[row0 + r] = s[r];
    }
}

// ============================================================
// Kernel 2: fused Gram(MMA) + w + weighted reduction
// z loaded as fp32 and converted to bf16 in the tile fill.
// grid = (16, 16, 8) = (jt, it, b); 256 threads (8 warps, 4x2)
// ============================================================
#define SM_WSTRIDE 68
#define SMEM_BYTES (2 * 128 * SM_WSTRIDE * 4 + 2 * 128 * 4)

extern __shared__ unsigned char smem_raw[];

__global__ void __launch_bounds__(256, 2)
main_kernel(const float* __restrict__ zf, const float* __restrict__ gt,
            const float* __restrict__ sigma, float* __restrict__ out) {
    uint32_t* zi  = (uint32_t*)smem_raw;
    uint32_t* zj  = zi + 128 * SM_WSTRIDE;
    float*    z2i = (float*)(zj + 128 * SM_WSTRIDE);
    float*    z2j = z2i + 128;

    const int jt = blockIdx.x, it = blockIdx.y, b = blockIdx.z;
    const int i0 = it * 128, j0 = jt * 128;
    const int tid = threadIdx.x;
    const int warp = tid >> 5, lane = tid & 31;

    // ---- L2 prefetch of this CTA's 128KB gt tile (overlaps z/MMA phase) ----
    {
        const char* gbase = (const char*)gt;
        #pragma unroll
        for (int p = 0; p < 4; p++) {
            int idx = tid + p * 256;                 // 0..1023
            int r = idx >> 3, c = idx & 7;
            const char* addr = gbase +
                ((size_t)(b * Tn + i0 + r) * Tn + j0) * 8 + (size_t)c * 128;
            asm volatile("prefetch.global.L2 [%0];" :: "l"(addr));
        }
    }

    // ---- load z tiles as fp32, convert to bf16 into smem ----
    const float4* zi4 = (const float4*)(zf + (size_t)(b * Tn + i0) * Dn);
    const float4* zj4 = (const float4*)(zf + (size_t)(b * Tn + j0) * Dn);
    #pragma unroll
    for (int p = 0; p < 16; p++) {
        const int idx = tid + p * 256;               // 0..4095
        const int r = idx >> 5, f = idx & 31;        // row, float4-in-row
        const float4 vi = zi4[idx];
        const float4 vj = zj4[idx];
        __nv_bfloat162 a0 = __floats2bfloat162_rn(vi.x, vi.y);
        __nv_bfloat162 a1 = __floats2bfloat162_rn(vi.z, vi.w);
        __nv_bfloat162 b0 = __floats2bfloat162_rn(vj.x, vj.y);
        __nv_bfloat162 b1 = __floats2bfloat162_rn(vj.z, vj.w);
        uint2 oi, oj;
        oi.x = *reinterpret_cast<uint32_t*>(&a0);
        oi.y = *reinterpret_cast<uint32_t*>(&a1);
        oj.x = *reinterpret_cast<uint32_t*>(&b0);
        oj.y = *reinterpret_cast<uint32_t*>(&b1);
        *((uint2*)(zi + r * SM_WSTRIDE + f * 2)) = oi;
        *((uint2*)(zj + r * SM_WSTRIDE + f * 2)) = oj;
    }
    if (tid < 128) z2i[tid] = g_z2[b * Tn + i0 + tid];
    else           z2j[tid - 128] = g_z2[b * Tn + j0 + (tid - 128)];
    __syncthreads();

    // ---- Gram 128x128 via mma.sync m16n8k16 bf16, ldmatrix operands ----
    const int wm = warp & 3, wn = warp >> 2;     // 4 x 2 warp grid
    const int rowBase = wm * 32, colBase = wn * 64;
    const int gr = lane >> 2, q = lane & 3;

    const uint32_t ziB = smem_u32(zi), zjB = smem_u32(zj);
    const int la = lane & 15, ha = lane >> 4;
    uint32_t aAddr0 = ziB + (uint32_t)((rowBase + la) * SM_WSTRIDE + ha * 4) * 4;
    uint32_t aAddr1 = aAddr0 + 16 * SM_WSTRIDE * 4;
    const int gq = lane >> 3;
    uint32_t bAddr = zjB + (uint32_t)((colBase + (gq >> 1) * 8 + (lane & 7)) * SM_WSTRIDE
                                      + (gq & 1) * 4) * 4;
    const uint32_t FN_STRIDE = 16 * SM_WSTRIDE * 4;

    float acc[2][8][4];
    #pragma unroll
    for (int fm = 0; fm < 2; fm++)
        #pragma unroll
        for (int fn = 0; fn < 8; fn++)
            #pragma unroll
            for (int v = 0; v < 4; v++) acc[fm][fn][v] = 0.f;

    #pragma unroll
    for (int ks = 0; ks < 8; ks++) {
        const uint32_t ko = ks * 32;
        uint32_t a[2][4], bb[4][4];
        LDSM_X4(a[0][0], a[0][1], a[0][2], a[0][3], aAddr0 + ko);
        LDSM_X4(a[1][0], a[1][1], a[1][2], a[1][3], aAddr1 + ko);
        #pragma unroll
        for (int p = 0; p < 4; p++)
            LDSM_X4(bb[p][0], bb[p][1], bb[p][2], bb[p][3], bAddr + p * FN_STRIDE + ko);

        #pragma unroll
        for (int p = 0; p < 4; p++) {
            #pragma unroll
            for (int s = 0; s < 2; s++) {
                const int fn = 2 * p + s;
                const uint32_t b0 = bb[p][2 * s], b1 = bb[p][2 * s + 1];
                #pragma unroll
                for (int fm = 0; fm < 2; fm++) {
                    asm volatile(
                        "mma.sync.aligned.m16n8k16.row.col.f32.bf16.bf16.f32 "
                        "{%0,%1,%2,%3}, {%4,%5,%6,%7}, {%8,%9}, {%0,%1,%2,%3};"
                        : "+f"(acc[fm][fn][0]), "+f"(acc[fm][fn][1]),
                          "+f"(acc[fm][fn][2]), "+f"(acc[fm][fn][3])
                        : "r"(a[fm][0]), "r"(a[fm][1]), "r"(a[fm][2]), "r"(a[fm][3]),
                          "r"(b0), "r"(b1));
                }
            }
        }
    }

    // ---- epilogue: stream gt (L2-hot), compute w, weighted accumulate ----
    const float sg0 = sigma[0], sg1 = sigma[1];
    const float c0 = 1.0f / (2.0f * sg0 * sg0), c1 = 1.0f / (2.0f * sg1 * sg1);
    const float4* gt4 = (const float4*)gt;       // {g(j,0),g(j,1),g(j+1,0),g(j+1,1)}
    float sum = 0.f;

    #pragma unroll
    for (int fm = 0; fm < 2; fm++) {
        const int ri = rowBase + fm * 16 + gr;
        const float z2a = z2i[ri];
        const float z2b = z2i[ri + 8];
        const size_t base0 = (size_t)(b * Tn + i0 + ri) * Tn + j0;
        const size_t base1 = base0 + (size_t)8 * Tn;
        #pragma unroll
        for (int fn = 0; fn < 8; fn++) {
            const int jj = colBase + fn * 8 + 2 * q;   // local col (even)
            const float zj0 = z2j[jj], zj1 = z2j[jj + 1];
            const float4 gA = gt4[(base0 + jj) >> 1];
            const float4 gB = gt4[(base1 + jj) >> 1];
            const float w00 = __expf(-(gA.x * gA.x * c0 + gA.y * gA.y * c1));
            const float w01 = __expf(-(gA.z * gA.z * c0 + gA.w * gA.w * c1));
            const float w10 = __expf(-(gB.x * gB.x * c0 + gB.y * gB.y * c1));
            const float w11 = __expf(-(gB.z * gB.z * c0 + gB.w * gB.w * c1));
            sum += w00 * (z2a + zj0 - 2.f * acc[fm][fn][0]);
            sum += w01 * (z2a + zj1 - 2.f * acc[fm][fn][1]);
            sum += w10 * (z2b + zj0 - 2.f * acc[fm][fn][2]);
            sum += w11 * (z2b + zj1 - 2.f * acc[fm][fn][3]);
        }
    }

    // ---- block reduce -> per-CTA partial ----
    #pragma unroll
    for (int o = 16; o; o >>= 1) sum += __shfl_xor_sync(0xffffffffu, sum, o);
    __shared__ float wsum[8];
    __shared__ int isLast;
    if (lane == 0) wsum[warp] = sum;
    __syncthreads();
    if (tid == 0) {
        float t = 0.f;
        #pragma unroll
        for (int w = 0; w < 8; w++) t += wsum[w];
        g_part[(b * 16 + it) * 16 + jt] = (double)t;
        __threadfence();
        int old = atomicAdd(&g_ticket, 1);
        isLast = (old == NPART - 1);
    }
    __syncthreads();

    // ---- last CTA: deterministic final reduce (fixed index order) ----
    if (isLast) {
        double s = 0.0;
        #pragma unroll
        for (int k = 0; k < NPART / 256; k++)
            s += g_part[tid * (NPART / 256) + k];
        __shared__ double sh[256];
        sh[tid] = s;
        __syncthreads();
        for (int o = 128; o; o >>= 1) {
            if (tid < o) sh[tid] += sh[tid + o];
            __syncthreads();
        }
        if (tid == 0) {
            out[0] = (float)(sh[0] / ((double)Bn * (double)Tn * (double)Tn));
            g_ticket = 0;   // reset for next graph replay
        }
    }
}

// ============================================================
extern "C" void kernel_launch(void* const* d_in, const int* in_sizes, int n_in,
                              void* d_out, int out_size) {
    const float *z = nullptr, *gt = nullptr, *sg = nullptr;
    for (int i = 0; i < n_in; i++) {
        if (in_sizes[i] == Bn * Tn * Dn)      z  = (const float*)d_in[i];
        else if (in_sizes[i] == 2)            sg = (const float*)d_in[i];
        else                                  gt = (const float*)d_in[i];
    }

    cudaFuncSetAttribute(main_kernel,
                         cudaFuncAttributeMaxDynamicSharedMemorySize, SMEM_BYTES);

    z2_kernel<<<Bn * Tn / 32, 256>>>(z);
    dim3 grid(16, 16, Bn);
    main_kernel<<<grid, 256, SMEM_BYTES>>>(z, gt, sg, (float*)d_out);
}

// round 16
// speedup vs baseline: 1.1710x; 1.0536x over previous
#include <cuda_runtime.h>
#include <cuda_bf16.h>
#include <cstdint>
#include <cstddef>

#define Bn 8
#define Tn 2048
#define Dn 128
#define NPAIR 136              // it <= jt pairs of 16 tiles
#define NPART (Bn * NPAIR)     // 1088 CTAs / partials

// ---- scratch (static device globals; no allocations) ----
__device__ __nv_bfloat16 g_zbf[Bn * Tn * Dn];   // 4 MB
__device__ float        g_z2[Bn * Tn];          // 64 KB
__device__ double       g_part[NPART];          // per-CTA partials
__device__ int          g_ticket;               // zero-init; last CTA resets

__device__ __forceinline__ uint32_t smem_u32(const void* p) {
    uint32_t a;
    asm("{ .reg .u64 t; cvta.to.shared.u64 t, %1; cvt.u32.u64 %0, t; }"
        : "=r"(a) : "l"(p));
    return a;
}

#define LDSM_X4(r0, r1, r2, r3, a) \
    asm volatile("ldmatrix.sync.aligned.m8n8.x4.shared.b16 {%0,%1,%2,%3}, [%4];" \
                 : "=r"(r0), "=r"(r1), "=r"(r2), "=r"(r3) : "r"(a))

// ============================================================
// Kernel 1: bf16 cast of z + per-row squared norms (4 rows/warp)
// ============================================================
__global__ void __launch_bounds__(256) prep_kernel(const float* __restrict__ z) {
    const int warp = threadIdx.x >> 5, lane = threadIdx.x & 31;
    const int row0 = blockIdx.x * 32 + warp * 4;
    float4 v[4];
    #pragma unroll
    for (int r = 0; r < 4; r++)
        v[r] = ((const float4*)(z + (size_t)(row0 + r) * Dn))[lane];

    #pragma unroll
    for (int r = 0; r < 4; r++) {
        __nv_bfloat162 p0 = __floats2bfloat162_rn(v[r].x, v[r].y);
        __nv_bfloat162 p1 = __floats2bfloat162_rn(v[r].z, v[r].w);
        uint2 o;
        o.x = *reinterpret_cast<uint32_t*>(&p0);
        o.y = *reinterpret_cast<uint32_t*>(&p1);
        ((uint2*)g_zbf)[(size_t)(row0 + r) * 32 + lane] = o;
    }

    float s[4];
    #pragma unroll
    for (int r = 0; r < 4; r++)
        s[r] = v[r].x * v[r].x + v[r].y * v[r].y + v[r].z * v[r].z + v[r].w * v[r].w;
    #pragma unroll
    for (int off = 16; off; off >>= 1) {
        #pragma unroll
        for (int r = 0; r < 4; r++)
            s[r] += __shfl_xor_sync(0xffffffffu, s[r], off);
    }
    if (lane == 0) {
        #pragma unroll
        for (int r = 0; r < 4; r++) g_z2[row0 + r] = s[r];
    }
}

// ============================================================
// Kernel 2: one Gram per (it<=jt) tile pair; two epilogue passes
// grid = (136, 8) = (pair, b); 256 threads (8 warps, 4x2)
// ============================================================
#define SM_WSTRIDE 68
#define SMEM_BYTES (2 * 128 * SM_WSTRIDE * 4 + 2 * 128 * 4)

extern __shared__ unsigned char smem_raw[];

__global__ void __launch_bounds__(256, 2)
main_kernel(const float* __restrict__ gt, const float* __restrict__ sigma,
            float* __restrict__ out) {
    uint32_t* zi  = (uint32_t*)smem_raw;
    uint32_t* zj  = zi + 128 * SM_WSTRIDE;
    float*    z2i = (float*)(zj + 128 * SM_WSTRIDE);
    float*    z2j = z2i + 128;

    // decode (it, jt) with it <= jt from pair index
    int p = blockIdx.x, it = 0;
    while (p >= 16 - it) { p -= 16 - it; it++; }
    const int jt = it + p;
    const int b = blockIdx.y;
    const int i0 = it * 128, j0 = jt * 128;
    const int offDiag = (it != jt);
    const int tid = threadIdx.x;
    const int warp = tid >> 5, lane = tid & 31;

    // ---- L2 prefetch of this CTA's gt tile(s) ----
    {
        const char* gbase = (const char*)gt;
        #pragma unroll
        for (int pp = 0; pp < 4; pp++) {
            int idx = tid + pp * 256;                // 0..1023
            int r = idx >> 3, c = idx & 7;
            const char* a1 = gbase +
                ((size_t)(b * Tn + i0 + r) * Tn + j0) * 8 + (size_t)c * 128;
            asm volatile("prefetch.global.L2 [%0];" :: "l"(a1));
            if (offDiag) {
                const char* a2 = gbase +
                    ((size_t)(b * Tn + j0 + r) * Tn + i0) * 8 + (size_t)c * 128;
                asm volatile("prefetch.global.L2 [%0];" :: "l"(a2));
            }
        }
    }

    // ---- load z tiles (bf16, 16B vectors) ----
    const uint4* zsrc = (const uint4*)g_zbf;     // one row = 16 uint4
    #pragma unroll
    for (int pp = 0; pp < 8; pp++) {
        int idx = tid + pp * 256;                // 0..2047
        int r = idx >> 4, c = idx & 15;
        uint4 vi = zsrc[(size_t)(b * Tn + i0 + r) * 16 + c];
        *((uint4*)(zi + r * SM_WSTRIDE + c * 4)) = vi;
        uint4 vj = zsrc[(size_t)(b * Tn + j0 + r) * 16 + c];
        *((uint4*)(zj + r * SM_WSTRIDE + c * 4)) = vj;
    }
    if (tid < 128) z2i[tid] = g_z2[b * Tn + i0 + tid];
    else           z2j[tid - 128] = g_z2[b * Tn + j0 + (tid - 128)];
    __syncthreads();

    // ---- Gram 128x128 via mma.sync m16n8k16 bf16, ldmatrix operands ----
    const int wm = warp & 3, wn = warp >> 2;     // 4 x 2 warp grid
    const int rowBase = wm * 32, colBase = wn * 64;
    const int gr = lane >> 2, q = lane & 3;

    const uint32_t ziB = smem_u32(zi), zjB = smem_u32(zj);
    const int la = lane & 15, ha = lane >> 4;
    uint32_t aAddr0 = ziB + (uint32_t)((rowBase + la) * SM_WSTRIDE + ha * 4) * 4;
    uint32_t aAddr1 = aAddr0 + 16 * SM_WSTRIDE * 4;
    const int gq = lane >> 3;
    uint32_t bAddr = zjB + (uint32_t)((colBase + (gq >> 1) * 8 + (lane & 7)) * SM_WSTRIDE
                                      + (gq & 1) * 4) * 4;
    const uint32_t FN_STRIDE = 16 * SM_WSTRIDE * 4;

    float acc[2][8][4];
    #pragma unroll
    for (int fm = 0; fm < 2; fm++)
        #pragma unroll
        for (int fn = 0; fn < 8; fn++)
            #pragma unroll
            for (int v = 0; v < 4; v++) acc[fm][fn][v] = 0.f;

    #pragma unroll
    for (int ks = 0; ks < 8; ks++) {
        const uint32_t ko = ks * 32;
        uint32_t a[2][4], bb[4][4];
        LDSM_X4(a[0][0], a[0][1], a[0][2], a[0][3], aAddr0 + ko);
        LDSM_X4(a[1][0], a[1][1], a[1][2], a[1][3], aAddr1 + ko);
        #pragma unroll
        for (int pp = 0; pp < 4; pp++)
            LDSM_X4(bb[pp][0], bb[pp][1], bb[pp][2], bb[pp][3], bAddr + pp * FN_STRIDE + ko);

        #pragma unroll
        for (int pp = 0; pp < 4; pp++) {
            #pragma unroll
            for (int s = 0; s < 2; s++) {
                const int fn = 2 * pp + s;
                const uint32_t b0 = bb[pp][2 * s], b1 = bb[pp][2 * s + 1];
                #pragma unroll
                for (int fm = 0; fm < 2; fm++) {
                    asm volatile(
                        "mma.sync.aligned.m16n8k16.row.col.f32.bf16.bf16.f32 "
                        "{%0,%1,%2,%3}, {%4,%5,%6,%7}, {%8,%9}, {%0,%1,%2,%3};"
                        : "+f"(acc[fm][fn][0]), "+f"(acc[fm][fn][1]),
                          "+f"(acc[fm][fn][2]), "+f"(acc[fm][fn][3])
                        : "r"(a[fm][0]), "r"(a[fm][1]), "r"(a[fm][2]), "r"(a[fm][3]),
                          "r"(b0), "r"(b1));
                }
            }
        }
    }

    // ---- epilogue constants ----
    const float sg0 = sigma[0], sg1 = sigma[1];
    const float c0 = 1.0f / (2.0f * sg0 * sg0), c1 = 1.0f / (2.0f * sg1 * sg1);
    const float4* gt4 = (const float4*)gt;       // {g(j,0),g(j,1),g(j+1,0),g(j+1,1)}
    float sum = 0.f;

    // ---- pass 1: rows = i-tile, cols = j-tile (identical to R10-gold) ----
    #pragma unroll
    for (int fm = 0; fm < 2; fm++) {
        const int ri = rowBase + fm * 16 + gr;
        const float z2a = z2i[ri];
        const float z2b = z2i[ri + 8];
        const size_t base0 = (size_t)(b * Tn + i0 + ri) * Tn + j0;
        const size_t base1 = base0 + (size_t)8 * Tn;
        #pragma unroll
        for (int fn = 0; fn < 8; fn++) {
            const int jj = colBase + fn * 8 + 2 * q;   // local col (even)
            const float zj0 = z2j[jj], zj1 = z2j[jj + 1];
            const float4 gA = gt4[(base0 + jj) >> 1];
            const float4 gB = gt4[(base1 + jj) >> 1];
            const float w00 = __expf(-(gA.x * gA.x * c0 + gA.y * gA.y * c1));
            const float w01 = __expf(-(gA.z * gA.z * c0 + gA.w * gA.w * c1));
            const float w10 = __expf(-(gB.x * gB.x * c0 + gB.y * gB.y * c1));
            const float w11 = __expf(-(gB.z * gB.z * c0 + gB.w * gB.w * c1));
            sum += w00 * (z2a + zj0 - 2.f * acc[fm][fn][0]);
            sum += w01 * (z2a + zj1 - 2.f * acc[fm][fn][1]);
            sum += w10 * (z2b + zj0 - 2.f * acc[fm][fn][2]);
            sum += w11 * (z2b + zj1 - 2.f * acc[fm][fn][3]);
        }
    }

    // ---- pass 2 (off-diagonal): rows = j-tile, cols = i-tile, G transposed ----
    if (offDiag) {
        const float2* gt2 = (const float2*)gt;   // element (i,j) = index i*Tn + j
        #pragma unroll
        for (int fm = 0; fm < 2; fm++) {
            const int ri = rowBase + fm * 16 + gr;     // column index now
            const float z2a = z2i[ri];
            const float z2b = z2i[ri + 8];
            #pragma unroll
            for (int fn = 0; fn < 8; fn++) {
                const int jj = colBase + fn * 8 + 2 * q;   // row index base
                const float zj0 = z2j[jj], zj1 = z2j[jj + 1];
                const size_t e0 = (size_t)(b * Tn + j0 + jj) * Tn + i0 + ri;
                const float2 gA0 = gt2[e0];            // (jj,   ri)
                const float2 gA8 = gt2[e0 + 8];        // (jj,   ri+8)
                const float2 gB0 = gt2[e0 + Tn];       // (jj+1, ri)
                const float2 gB8 = gt2[e0 + Tn + 8];   // (jj+1, ri+8)
                const float w00 = __expf(-(gA0.x * gA0.x * c0 + gA0.y * gA0.y * c1));
                const float w01 = __expf(-(gB0.x * gB0.x * c0 + gB0.y * gB0.y * c1));
                const float w10 = __expf(-(gA8.x * gA8.x * c0 + gA8.y * gA8.y * c1));
                const float w11 = __expf(-(gB8.x * gB8.x * c0 + gB8.y * gB8.y * c1));
                sum += w00 * (zj0 + z2a - 2.f * acc[fm][fn][0]);  // (jj,   ri)
                sum += w01 * (zj1 + z2a - 2.f * acc[fm][fn][1]);  // (jj+1, ri)
                sum += w10 * (zj0 + z2b - 2.f * acc[fm][fn][2]);  // (jj,   ri+8)
                sum += w11 * (zj1 + z2b - 2.f * acc[fm][fn][3]);  // (jj+1, ri+8)
            }
        }
    }

    // ---- block reduce -> per-CTA partial ----
    #pragma unroll
    for (int o = 16; o; o >>= 1) sum += __shfl_xor_sync(0xffffffffu, sum, o);
    __shared__ float wsum[8];
    __shared__ int isLast;
    if (lane == 0) wsum[warp] = sum;
    __syncthreads();
    if (tid == 0) {
        float t = 0.f;
        #pragma unroll
        for (int w = 0; w < 8; w++) t += wsum[w];
        g_part[b * NPAIR + blockIdx.x] = (double)t;
        __threadfence();
        int old = atomicAdd(&g_ticket, 1);
        isLast = (old == NPART - 1);
    }
    __syncthreads();

    // ---- last CTA: deterministic final reduce (fixed index order) ----
    if (isLast) {
        double s = 0.0;
        for (int i = tid; i < NPART; i += 256) s += g_part[i];
        __shared__ double sh[256];
        sh[tid] = s;
        __syncthreads();
        for (int o = 128; o; o >>= 1) {
            if (tid < o) sh[tid] += sh[tid + o];
            __syncthreads();
        }
        if (tid == 0) {
            out[0] = (float)(sh[0] / ((double)Bn * (double)Tn * (double)Tn));
            g_ticket = 0;   // reset for next graph replay
        }
    }
}

// ============================================================
extern "C" void kernel_launch(void* const* d_in, const int* in_sizes, int n_in,
                              void* d_out, int out_size) {
    const float *z = nullptr, *gt = nullptr, *sg = nullptr;
    for (int i = 0; i < n_in; i++) {
        if (in_sizes[i] == Bn * Tn * Dn)      z  = (const float*)d_in[i];
        else if (in_sizes[i] == 2)            sg = (const float*)d_in[i];
        else                                  gt = (const float*)d_in[i];
    }

    cudaFuncSetAttribute(main_kernel,
                         cudaFuncAttributeMaxDynamicSharedMemorySize, SMEM_BYTES);

    prep_kernel<<<Bn * Tn / 32, 256>>>(z);
    dim3 grid(NPAIR, Bn);
    main_kernel<<<grid, 256, SMEM_BYTES>>>(gt, sg, (float*)d_out);
}